// round 1
// baseline (speedup 1.0000x reference)
#include <cuda_runtime.h>
#include <math.h>

// ---------------- problem constants (fixed by reference setup_inputs) --------
#define N_NODES 100000
#define N_EDGES 50000
#define NNZ     400000
#define IN_CH   64
#define HID     256

// ---------------- device scratch (static, no runtime alloc) ------------------
__device__ float g_edge_sum[N_EDGES];
__device__ float g_node_sum[N_NODES];
__device__ float g_edge_card[N_EDGES];
__device__ float g_node_card[N_NODES];
__device__ float g_d0[N_NODES];
__device__ float g_d1[N_EDGES];
__device__ float g_vals_n[NNZ];
__device__ float g_vals_t[NNZ];
__device__ int   g_counts[N_NODES];
__device__ int   g_offs[N_NODES];
__device__ int   g_cursor[N_NODES];
__device__ int   g_csr[NNZ];
__device__ int   g_bsum[128];
__device__ float g_agg[N_EDGES * HID];
__device__ float g_x1 [N_EDGES * HID];
__device__ float g_M1 [N_EDGES * HID];
__device__ float g_x0 [N_NODES * HID];
__device__ float g_pooled[HID];

// ---------------- small init ------------------------------------------------
__global__ void k_zero_small() {
    int i = blockIdx.x * blockDim.x + threadIdx.x;
    if (i < N_NODES) { g_node_sum[i] = 0.f; g_d0[i] = 0.f; g_counts[i] = 0; g_cursor[i] = 0; }
    if (i < N_EDGES) { g_edge_sum[i] = 0.f; g_d1[i] = 0.f; }
    if (i < HID)     { g_pooled[i] = 0.f; }
}

// ---------------- normalization ----------------------------------------------
__global__ void k_seg_sums(const float* __restrict__ vals, const int* __restrict__ rows,
                           const int* __restrict__ cols) {
    int k = blockIdx.x * blockDim.x + threadIdx.x;
    if (k >= NNZ) return;
    float v = vals[k];
    atomicAdd(&g_edge_sum[cols[k]], v);
    atomicAdd(&g_node_sum[rows[k]], v);
}

__global__ void k_cards() {
    int i = blockIdx.x * blockDim.x + threadIdx.x;
    if (i < N_NODES) g_node_card[i] = powf(g_node_sum[i], -0.5f);
    if (i < N_EDGES) g_edge_card[i] = powf(g_edge_sum[i], -1.5f);
}

__global__ void k_dsums(const float* __restrict__ vals, const int* __restrict__ rows,
                        const int* __restrict__ cols) {
    int k = blockIdx.x * blockDim.x + threadIdx.x;
    if (k >= NNZ) return;
    float nz = (vals[k] != 0.f) ? 1.f : 0.f;
    atomicAdd(&g_d0[rows[k]], g_edge_card[cols[k]] * nz);
    atomicAdd(&g_d1[cols[k]], g_node_card[rows[k]] * nz);
}

__global__ void k_valsnt(const float* __restrict__ vals, const int* __restrict__ rows,
                         const int* __restrict__ cols) {
    int k = blockIdx.x * blockDim.x + threadIdx.x;
    if (k >= NNZ) return;
    int r = rows[k], c = cols[k];
    float v = vals[k];
    g_vals_n[k] = v * g_edge_card[c] / g_d0[r];
    g_vals_t[k] = v * g_node_card[r] / g_d1[c];
    atomicAdd(&g_counts[r], 1);   // degree counts for row-CSR
}

// ---------------- exclusive scan of g_counts -> g_offs (two-level) ----------
__global__ void k_scanA() {
    __shared__ int sh[1024];
    int b = blockIdx.x, t = threadIdx.x;
    int i = b * 1024 + t;
    int v = (i < N_NODES) ? g_counts[i] : 0;
    sh[t] = v;
    __syncthreads();
    for (int d = 1; d < 1024; d <<= 1) {
        int add = (t >= d) ? sh[t - d] : 0;
        __syncthreads();
        sh[t] += add;
        __syncthreads();
    }
    if (i < N_NODES) g_offs[i] = sh[t] - v;   // exclusive
    if (t == 1023) g_bsum[b] = sh[t];
}

__global__ void k_scanB(int nb) {
    if (threadIdx.x == 0) {
        int acc = 0;
        for (int i = 0; i < nb; i++) { int t = g_bsum[i]; g_bsum[i] = acc; acc += t; }
    }
}

__global__ void k_scanC() {
    int i = blockIdx.x * blockDim.x + threadIdx.x;
    if (i < N_NODES) g_offs[i] += g_bsum[i >> 10];
}

__global__ void k_fill_csr(const int* __restrict__ rows) {
    int k = blockIdx.x * blockDim.x + threadIdx.x;
    if (k >= NNZ) return;
    int v = rows[k];
    int p = g_offs[v] + atomicAdd(&g_cursor[v], 1);
    g_csr[p] = k;
}

// ---------------- node -> edge aggregation (cols sorted: binary search) ------
__device__ __forceinline__ int lower_bound_i(const int* __restrict__ a, int n, int v) {
    int lo = 0, hi = n;
    while (lo < hi) { int m = (lo + hi) >> 1; if (a[m] < v) lo = m + 1; else hi = m; }
    return lo;
}

__global__ void k_agg_edges(const float* __restrict__ x, const int* __restrict__ rows,
                            const int* __restrict__ cols, int dim) {
    int e = blockIdx.x;
    int c = threadIdx.x;
    int lo = lower_bound_i(cols, NNZ, e);
    int hi = lower_bound_i(cols, NNZ, e + 1);
    float acc = 0.f;
    for (int k = lo; k < hi; k++)
        acc += g_vals_t[k] * x[rows[k] * dim + c];
    g_agg[e * dim + c] = acc;
}

// ---------------- fp32 tiled SGEMM: C = A(MxK) @ B(KxN) [+bias][relu] --------
__global__ __launch_bounds__(256)
void k_sgemm(const float* __restrict__ A, const float* __restrict__ B,
             const float* __restrict__ bias, float* __restrict__ C,
             int M, int N, int K, int relu) {
    __shared__ float As[16][64];
    __shared__ float Bs[16][64];
    int bm = blockIdx.y * 64, bn = blockIdx.x * 64;
    int tid = threadIdx.x;
    int tm = (tid >> 4) << 2;   // 0..60
    int tn = (tid & 15) << 2;   // 0..60
    float acc[4][4] = {};
    for (int k0 = 0; k0 < K; k0 += 16) {
        #pragma unroll
        for (int i = tid; i < 64 * 16; i += 256) {
            int m = i >> 4, k = i & 15;
            As[k][m] = (bm + m < M) ? A[(bm + m) * K + k0 + k] : 0.f;
        }
        #pragma unroll
        for (int i = tid; i < 16 * 64; i += 256) {
            int k = i >> 6, n = i & 63;
            Bs[k][n] = B[(k0 + k) * N + bn + n];
        }
        __syncthreads();
        #pragma unroll
        for (int k = 0; k < 16; k++) {
            float4 a4 = *reinterpret_cast<const float4*>(&As[k][tm]);
            float4 b4 = *reinterpret_cast<const float4*>(&Bs[k][tn]);
            float a[4] = {a4.x, a4.y, a4.z, a4.w};
            float b[4] = {b4.x, b4.y, b4.z, b4.w};
            #pragma unroll
            for (int i = 0; i < 4; i++)
                #pragma unroll
                for (int j = 0; j < 4; j++)
                    acc[i][j] += a[i] * b[j];
        }
        __syncthreads();
    }
    #pragma unroll
    for (int i = 0; i < 4; i++) {
        int m = bm + tm + i;
        if (m >= M) continue;
        #pragma unroll
        for (int j = 0; j < 4; j++) {
            int n = bn + tn + j;
            float v = acc[i][j] + (bias ? bias[n] : 0.f);
            if (relu) v = fmaxf(v, 0.f);
            C[m * N + n] = v;
        }
    }
}

// ---------------- edge -> node gather via row-CSR (+bias, relu) --------------
__global__ void k_gather_nodes(const float* __restrict__ b0, const int* __restrict__ cols) {
    int v = blockIdx.x;
    int c = threadIdx.x;
    int off = g_offs[v];
    int n   = g_counts[v];
    float acc = b0[c];
    for (int j = 0; j < n; j++) {
        int k = g_csr[off + j];
        acc += g_vals_n[k] * g_M1[cols[k] * HID + c];
    }
    g_x0[v * HID + c] = fmaxf(acc, 0.f);
}

// ---------------- max pool over nodes + final dot ----------------------------
__global__ void k_maxpool() {
    int c = threadIdx.x;
    int rb = blockIdx.x;
    const int RPB = (N_NODES + 399) / 400;
    int r0 = rb * RPB;
    int r1 = min(r0 + RPB, N_NODES);
    float m = 0.f;   // relu outputs are >= 0
    for (int r = r0; r < r1; r++)
        m = fmaxf(m, g_x0[r * HID + c]);
    atomicMax((int*)&g_pooled[c], __float_as_int(m));   // valid for nonneg floats
}

__global__ void k_final(const float* __restrict__ lin_w, const float* __restrict__ lin_b,
                        float* __restrict__ out) {
    __shared__ float sh[256];
    int c = threadIdx.x;
    sh[c] = g_pooled[c] * lin_w[c];
    __syncthreads();
    for (int s = 128; s > 0; s >>= 1) {
        if (c < s) sh[c] += sh[c + s];
        __syncthreads();
    }
    if (c == 0) out[0] = sh[0] + lin_b[0];
}

// ---------------- launch ------------------------------------------------------
extern "C" void kernel_launch(void* const* d_in, const int* in_sizes, int n_in,
                              void* d_out, int out_size) {
    const float* x_in  = (const float*)d_in[0];
    const float* vals  = (const float*)d_in[1];
    const int*   rows  = (const int*)  d_in[2];
    const int*   cols  = (const int*)  d_in[3];
    const float* W0_l0 = (const float*)d_in[4];
    const float* W1_l0 = (const float*)d_in[5];
    const float* b1_l0 = (const float*)d_in[6];
    const float* b0_l0 = (const float*)d_in[7];
    const float* W0_l1 = (const float*)d_in[8];
    const float* W1_l1 = (const float*)d_in[9];
    const float* b1_l1 = (const float*)d_in[10];
    const float* b0_l1 = (const float*)d_in[11];
    const float* lin_w = (const float*)d_in[12];
    const float* lin_b = (const float*)d_in[13];
    float* out = (float*)d_out;

    float *p_agg, *p_x1, *p_M1, *p_x0;
    cudaGetSymbolAddress((void**)&p_agg, g_agg);
    cudaGetSymbolAddress((void**)&p_x1,  g_x1);
    cudaGetSymbolAddress((void**)&p_M1,  g_M1);
    cudaGetSymbolAddress((void**)&p_x0,  g_x0);

    const int TB = 256;
    const int gN = (N_NODES + TB - 1) / TB;
    const int gZ = (NNZ + TB - 1) / TB;
    const int NBLK = (N_NODES + 1023) / 1024;

    // normalization + CSR build
    k_zero_small<<<gN, TB>>>();
    k_seg_sums<<<gZ, TB>>>(vals, rows, cols);
    k_cards<<<gN, TB>>>();
    k_dsums<<<gZ, TB>>>(vals, rows, cols);
    k_valsnt<<<gZ, TB>>>(vals, rows, cols);
    k_scanA<<<NBLK, 1024>>>();
    k_scanB<<<1, 32>>>(NBLK);
    k_scanC<<<gN, TB>>>();
    k_fill_csr<<<gZ, TB>>>(rows);

    dim3 gemm_grid(HID / 64, (N_EDGES + 63) / 64);

    // ---- layer 0 ----
    k_agg_edges<<<N_EDGES, IN_CH>>>(x_in, rows, cols, IN_CH);
    k_sgemm<<<gemm_grid, 256>>>(p_agg, W0_l0, b1_l0, p_x1, N_EDGES, HID, IN_CH, 1);
    k_sgemm<<<gemm_grid, 256>>>(p_x1, W1_l0, nullptr, p_M1, N_EDGES, HID, HID, 0);
    k_gather_nodes<<<N_NODES, HID>>>(b0_l0, cols);

    // ---- layer 1 ----
    k_agg_edges<<<N_EDGES, HID>>>(p_x0, rows, cols, HID);
    k_sgemm<<<gemm_grid, 256>>>(p_agg, W0_l1, b1_l1, p_x1, N_EDGES, HID, HID, 1);
    k_sgemm<<<gemm_grid, 256>>>(p_x1, W1_l1, nullptr, p_M1, N_EDGES, HID, HID, 0);
    k_gather_nodes<<<N_NODES, HID>>>(b0_l1, cols);

    // ---- pool + head ----
    k_maxpool<<<400, HID>>>();
    k_final<<<1, HID>>>(lin_w, lin_b, out);
}

// round 2
// speedup vs baseline: 2.6848x; 2.6848x over previous
#include <cuda_runtime.h>
#include <math.h>
#include <stdint.h>

// ---------------- problem constants (fixed by reference setup_inputs) --------
#define N_NODES 100000
#define N_EDGES 50000
#define NNZ     400000
#define IN_CH   64
#define HID     256

// ---------------- device scratch (static, no runtime alloc) ------------------
__device__ float g_edge_sum[N_EDGES];
__device__ float g_node_sum[N_NODES];
__device__ float g_edge_card[N_EDGES];
__device__ float g_node_card[N_NODES];
__device__ float g_d0[N_NODES];
__device__ float g_d1[N_EDGES];
__device__ float g_vals_n[NNZ];
__device__ float g_vals_t[NNZ];
__device__ int   g_counts[N_NODES];
__device__ int   g_offs[N_NODES];
__device__ int   g_cursor[N_NODES];
__device__ int   g_csr[NNZ];
__device__ int   g_bsum[128];
__device__ float g_agg[N_EDGES * HID];
__device__ float g_x1 [N_EDGES * HID];
__device__ float g_M1 [N_EDGES * HID];
__device__ float g_x0 [N_NODES * HID];
__device__ float g_pooled[HID];

// ---------------- small init ------------------------------------------------
__global__ void k_zero_small() {
    int i = blockIdx.x * blockDim.x + threadIdx.x;
    if (i < N_NODES) { g_node_sum[i] = 0.f; g_d0[i] = 0.f; g_counts[i] = 0; g_cursor[i] = 0; }
    if (i < N_EDGES) { g_edge_sum[i] = 0.f; g_d1[i] = 0.f; }
    if (i < HID)     { g_pooled[i] = 0.f; }
}

// ---------------- normalization ----------------------------------------------
__global__ void k_seg_sums(const float* __restrict__ vals, const int* __restrict__ rows,
                           const int* __restrict__ cols) {
    int k = blockIdx.x * blockDim.x + threadIdx.x;
    if (k >= NNZ) return;
    float v = vals[k];
    atomicAdd(&g_edge_sum[cols[k]], v);
    atomicAdd(&g_node_sum[rows[k]], v);
}

__global__ void k_cards() {
    int i = blockIdx.x * blockDim.x + threadIdx.x;
    if (i < N_NODES) g_node_card[i] = powf(g_node_sum[i], -0.5f);
    if (i < N_EDGES) g_edge_card[i] = powf(g_edge_sum[i], -1.5f);
}

__global__ void k_dsums(const float* __restrict__ vals, const int* __restrict__ rows,
                        const int* __restrict__ cols) {
    int k = blockIdx.x * blockDim.x + threadIdx.x;
    if (k >= NNZ) return;
    float nz = (vals[k] != 0.f) ? 1.f : 0.f;
    atomicAdd(&g_d0[rows[k]], g_edge_card[cols[k]] * nz);
    atomicAdd(&g_d1[cols[k]], g_node_card[rows[k]] * nz);
}

__global__ void k_valsnt(const float* __restrict__ vals, const int* __restrict__ rows,
                         const int* __restrict__ cols) {
    int k = blockIdx.x * blockDim.x + threadIdx.x;
    if (k >= NNZ) return;
    int r = rows[k], c = cols[k];
    float v = vals[k];
    g_vals_n[k] = v * g_edge_card[c] / g_d0[r];
    g_vals_t[k] = v * g_node_card[r] / g_d1[c];
    atomicAdd(&g_counts[r], 1);   // degree counts for row-CSR
}

// ---------------- exclusive scan of g_counts -> g_offs (two-level) ----------
__global__ void k_scanA() {
    __shared__ int sh[1024];
    int b = blockIdx.x, t = threadIdx.x;
    int i = b * 1024 + t;
    int v = (i < N_NODES) ? g_counts[i] : 0;
    sh[t] = v;
    __syncthreads();
    for (int d = 1; d < 1024; d <<= 1) {
        int add = (t >= d) ? sh[t - d] : 0;
        __syncthreads();
        sh[t] += add;
        __syncthreads();
    }
    if (i < N_NODES) g_offs[i] = sh[t] - v;   // exclusive
    if (t == 1023) g_bsum[b] = sh[t];
}

__global__ void k_scanB(int nb) {
    if (threadIdx.x == 0) {
        int acc = 0;
        for (int i = 0; i < nb; i++) { int t = g_bsum[i]; g_bsum[i] = acc; acc += t; }
    }
}

__global__ void k_scanC() {
    int i = blockIdx.x * blockDim.x + threadIdx.x;
    if (i < N_NODES) g_offs[i] += g_bsum[i >> 10];
}

__global__ void k_fill_csr(const int* __restrict__ rows) {
    int k = blockIdx.x * blockDim.x + threadIdx.x;
    if (k >= NNZ) return;
    int v = rows[k];
    int p = g_offs[v] + atomicAdd(&g_cursor[v], 1);
    g_csr[p] = k;
}

// ---------------- node -> edge aggregation (cols sorted: binary search) ------
__device__ __forceinline__ int lower_bound_i(const int* __restrict__ a, int n, int v) {
    int lo = 0, hi = n;
    while (lo < hi) { int m = (lo + hi) >> 1; if (a[m] < v) lo = m + 1; else hi = m; }
    return lo;
}

// dim = 64 scalar version (layer 0 input)
__global__ void k_agg_edges64(const float* __restrict__ x, const int* __restrict__ rows,
                              const int* __restrict__ cols) {
    int e = blockIdx.x;
    int c = threadIdx.x;   // 0..63
    int lo = lower_bound_i(cols, NNZ, e);
    int hi = lower_bound_i(cols, NNZ, e + 1);
    float acc = 0.f;
    for (int k = lo; k < hi; k++)
        acc += g_vals_t[k] * x[rows[k] * IN_CH + c];
    g_agg[e * IN_CH + c] = acc;
}

// dim = 256 float4 version (layer 1)
__global__ void k_agg_edges256(const float* __restrict__ x, const int* __restrict__ rows,
                               const int* __restrict__ cols) {
    int e = blockIdx.x;
    int c = threadIdx.x;   // 0..63 -> float4 lane
    int lo = lower_bound_i(cols, NNZ, e);
    int hi = lower_bound_i(cols, NNZ, e + 1);
    float4 acc = make_float4(0.f, 0.f, 0.f, 0.f);
    for (int k = lo; k < hi; k++) {
        float vt = g_vals_t[k];
        const float4* xr = reinterpret_cast<const float4*>(&x[rows[k] * HID]);
        float4 v = xr[c];
        acc.x += vt * v.x; acc.y += vt * v.y; acc.z += vt * v.z; acc.w += vt * v.w;
    }
    reinterpret_cast<float4*>(&g_agg[e * HID])[c] = acc;
}

// ---------------- TF32 tensor-core GEMM: C = A(MxK) @ B(Kx256) ---------------
// BM=128, BN=64, BK=32. 8 warps: 4 (M) x 2 (N), warp tile 32x32 via m16n8k8.
__device__ __forceinline__ uint32_t f2tf32(float f) {
    uint32_t u;
    asm("cvt.rna.tf32.f32 %0, %1;" : "=r"(u) : "f"(f));
    return u;
}

__device__ __forceinline__ void mma_tf32(float c[4],
                                         uint32_t a0, uint32_t a1, uint32_t a2, uint32_t a3,
                                         uint32_t b0, uint32_t b1) {
    asm volatile(
        "mma.sync.aligned.m16n8k8.row.col.f32.tf32.tf32.f32 "
        "{%0,%1,%2,%3}, {%4,%5,%6,%7}, {%8,%9}, {%0,%1,%2,%3};\n"
        : "+f"(c[0]), "+f"(c[1]), "+f"(c[2]), "+f"(c[3])
        : "r"(a0), "r"(a1), "r"(a2), "r"(a3), "r"(b0), "r"(b1));
}

__global__ __launch_bounds__(256, 2)
void k_mma_gemm(const float* __restrict__ A, const float* __restrict__ B,
                const float* __restrict__ bias, float* __restrict__ C,
                int M, int K, int relu) {
    __shared__ uint32_t As[128][36];   // stride 36: banks (4g+tig) conflict-free
    __shared__ uint32_t Bs[32][72];    // stride 72: banks (8tig+g) conflict-free
    const int N = HID;
    int tid = threadIdx.x;
    int lane = tid & 31, wid = tid >> 5;
    int wm = wid & 3, wn = wid >> 2;          // warp coords 4x2
    int g = lane >> 2, tig = lane & 3;        // groupID, threadInGroup
    int bm = blockIdx.y * 128, bn = blockIdx.x * 64;

    float acc[2][4][4];
    #pragma unroll
    for (int mi = 0; mi < 2; mi++)
        #pragma unroll
        for (int ni = 0; ni < 4; ni++)
            #pragma unroll
            for (int r = 0; r < 4; r++) acc[mi][ni][r] = 0.f;

    for (int k0 = 0; k0 < K; k0 += 32) {
        // stage A: 128 rows x 32 cols = 1024 float4 loads
        #pragma unroll
        for (int i = tid; i < 1024; i += 256) {
            int m = i >> 3, k4 = (i & 7) << 2;
            float4 v = make_float4(0.f, 0.f, 0.f, 0.f);
            if (bm + m < M)
                v = *reinterpret_cast<const float4*>(&A[(size_t)(bm + m) * K + k0 + k4]);
            As[m][k4 + 0] = f2tf32(v.x);
            As[m][k4 + 1] = f2tf32(v.y);
            As[m][k4 + 2] = f2tf32(v.z);
            As[m][k4 + 3] = f2tf32(v.w);
        }
        // stage B: 32 rows x 64 cols = 512 float4 loads
        #pragma unroll
        for (int i = tid; i < 512; i += 256) {
            int k = i >> 4, n4 = (i & 15) << 2;
            float4 v = *reinterpret_cast<const float4*>(&B[(size_t)(k0 + k) * N + bn + n4]);
            Bs[k][n4 + 0] = f2tf32(v.x);
            Bs[k][n4 + 1] = f2tf32(v.y);
            Bs[k][n4 + 2] = f2tf32(v.z);
            Bs[k][n4 + 3] = f2tf32(v.w);
        }
        __syncthreads();
        #pragma unroll
        for (int ks = 0; ks < 32; ks += 8) {
            uint32_t a[2][4], b[4][2];
            #pragma unroll
            for (int mi = 0; mi < 2; mi++) {
                int mrow = wm * 32 + mi * 16 + g;
                a[mi][0] = As[mrow    ][ks + tig];
                a[mi][1] = As[mrow + 8][ks + tig];
                a[mi][2] = As[mrow    ][ks + tig + 4];
                a[mi][3] = As[mrow + 8][ks + tig + 4];
            }
            #pragma unroll
            for (int ni = 0; ni < 4; ni++) {
                int ncol = wn * 32 + ni * 8 + g;
                b[ni][0] = Bs[ks + tig    ][ncol];
                b[ni][1] = Bs[ks + tig + 4][ncol];
            }
            #pragma unroll
            for (int mi = 0; mi < 2; mi++)
                #pragma unroll
                for (int ni = 0; ni < 4; ni++)
                    mma_tf32(acc[mi][ni], a[mi][0], a[mi][1], a[mi][2], a[mi][3],
                             b[ni][0], b[ni][1]);
        }
        __syncthreads();
    }

    // epilogue
    #pragma unroll
    for (int mi = 0; mi < 2; mi++) {
        #pragma unroll
        for (int ni = 0; ni < 4; ni++) {
            int row0 = bm + wm * 32 + mi * 16 + g;
            int col0 = bn + wn * 32 + ni * 8 + 2 * tig;
            float bv0 = bias ? bias[col0]     : 0.f;
            float bv1 = bias ? bias[col0 + 1] : 0.f;
            float v00 = acc[mi][ni][0] + bv0;
            float v01 = acc[mi][ni][1] + bv1;
            float v10 = acc[mi][ni][2] + bv0;
            float v11 = acc[mi][ni][3] + bv1;
            if (relu) {
                v00 = fmaxf(v00, 0.f); v01 = fmaxf(v01, 0.f);
                v10 = fmaxf(v10, 0.f); v11 = fmaxf(v11, 0.f);
            }
            if (row0 < M)
                *reinterpret_cast<float2*>(&C[(size_t)row0 * N + col0]) = make_float2(v00, v01);
            if (row0 + 8 < M)
                *reinterpret_cast<float2*>(&C[(size_t)(row0 + 8) * N + col0]) = make_float2(v10, v11);
        }
    }
}

// ---------------- edge -> node gather via row-CSR (+bias, relu), float4 ------
__global__ void k_gather_nodes(const float* __restrict__ b0, const int* __restrict__ cols) {
    int v = blockIdx.x;
    int c = threadIdx.x;   // 0..63 float4 lane
    int off = g_offs[v];
    int n   = g_counts[v];
    float4 acc = reinterpret_cast<const float4*>(b0)[c];
    for (int j = 0; j < n; j++) {
        int k = g_csr[off + j];
        float vn = g_vals_n[k];
        float4 m = reinterpret_cast<const float4*>(&g_M1[cols[k] * HID])[c];
        acc.x += vn * m.x; acc.y += vn * m.y; acc.z += vn * m.z; acc.w += vn * m.w;
    }
    acc.x = fmaxf(acc.x, 0.f); acc.y = fmaxf(acc.y, 0.f);
    acc.z = fmaxf(acc.z, 0.f); acc.w = fmaxf(acc.w, 0.f);
    reinterpret_cast<float4*>(&g_x0[v * HID])[c] = acc;
}

// ---------------- max pool over nodes + final dot ----------------------------
__global__ void k_maxpool() {
    int c = threadIdx.x;
    int rb = blockIdx.x;
    const int RPB = (N_NODES + 399) / 400;
    int r0 = rb * RPB;
    int r1 = min(r0 + RPB, N_NODES);
    float m = 0.f;   // relu outputs are >= 0
    for (int r = r0; r < r1; r++)
        m = fmaxf(m, g_x0[r * HID + c]);
    atomicMax((int*)&g_pooled[c], __float_as_int(m));   // valid for nonneg floats
}

__global__ void k_final(const float* __restrict__ lin_w, const float* __restrict__ lin_b,
                        float* __restrict__ out) {
    __shared__ float sh[256];
    int c = threadIdx.x;
    sh[c] = g_pooled[c] * lin_w[c];
    __syncthreads();
    for (int s = 128; s > 0; s >>= 1) {
        if (c < s) sh[c] += sh[c + s];
        __syncthreads();
    }
    if (c == 0) out[0] = sh[0] + lin_b[0];
}

// ---------------- launch ------------------------------------------------------
extern "C" void kernel_launch(void* const* d_in, const int* in_sizes, int n_in,
                              void* d_out, int out_size) {
    const float* x_in  = (const float*)d_in[0];
    const float* vals  = (const float*)d_in[1];
    const int*   rows  = (const int*)  d_in[2];
    const int*   cols  = (const int*)  d_in[3];
    const float* W0_l0 = (const float*)d_in[4];
    const float* W1_l0 = (const float*)d_in[5];
    const float* b1_l0 = (const float*)d_in[6];
    const float* b0_l0 = (const float*)d_in[7];
    const float* W0_l1 = (const float*)d_in[8];
    const float* W1_l1 = (const float*)d_in[9];
    const float* b1_l1 = (const float*)d_in[10];
    const float* b0_l1 = (const float*)d_in[11];
    const float* lin_w = (const float*)d_in[12];
    const float* lin_b = (const float*)d_in[13];
    float* out = (float*)d_out;

    float *p_agg, *p_x1, *p_M1, *p_x0;
    cudaGetSymbolAddress((void**)&p_agg, g_agg);
    cudaGetSymbolAddress((void**)&p_x1,  g_x1);
    cudaGetSymbolAddress((void**)&p_M1,  g_M1);
    cudaGetSymbolAddress((void**)&p_x0,  g_x0);

    const int TB = 256;
    const int gN = (N_NODES + TB - 1) / TB;
    const int gZ = (NNZ + TB - 1) / TB;
    const int NBLK = (N_NODES + 1023) / 1024;

    // normalization + CSR build
    k_zero_small<<<gN, TB>>>();
    k_seg_sums<<<gZ, TB>>>(vals, rows, cols);
    k_cards<<<gN, TB>>>();
    k_dsums<<<gZ, TB>>>(vals, rows, cols);
    k_valsnt<<<gZ, TB>>>(vals, rows, cols);
    k_scanA<<<NBLK, 1024>>>();
    k_scanB<<<1, 32>>>(NBLK);
    k_scanC<<<gN, TB>>>();
    k_fill_csr<<<gZ, TB>>>(rows);

    dim3 gemm_grid(HID / 64, (N_EDGES + 127) / 128);

    // ---- layer 0 ----
    k_agg_edges64<<<N_EDGES, IN_CH>>>(x_in, rows, cols);
    k_mma_gemm<<<gemm_grid, 256>>>(p_agg, W0_l0, b1_l0, p_x1, N_EDGES, IN_CH, 1);
    k_mma_gemm<<<gemm_grid, 256>>>(p_x1, W1_l0, nullptr, p_M1, N_EDGES, HID, 0);
    k_gather_nodes<<<N_NODES, 64>>>(b0_l0, cols);

    // ---- layer 1 ----
    k_agg_edges256<<<N_EDGES, 64>>>(p_x0, rows, cols);
    k_mma_gemm<<<gemm_grid, 256>>>(p_agg, W0_l1, b1_l1, p_x1, N_EDGES, HID, 1);
    k_mma_gemm<<<gemm_grid, 256>>>(p_x1, W1_l1, nullptr, p_M1, N_EDGES, HID, 0);
    k_gather_nodes<<<N_NODES, 64>>>(b0_l1, cols);

    // ---- pool + head ----
    k_maxpool<<<400, HID>>>();
    k_final<<<1, HID>>>(lin_w, lin_b, out);
}

// round 3
// speedup vs baseline: 3.0389x; 1.1319x over previous
#include <cuda_runtime.h>
#include <math.h>
#include <stdint.h>

// ---------------- problem constants (fixed by reference setup_inputs) --------
#define N_NODES 100000
#define N_EDGES 50000
#define NNZ     400000
#define IN_CH   64
#define HID     256

// ---------------- device scratch (static, no runtime alloc) ------------------
__device__ float g_edge_sum[N_EDGES];
__device__ float g_node_sum[N_NODES];
__device__ float g_edge_card[N_EDGES];
__device__ float g_node_card[N_NODES];
__device__ float g_d0[N_NODES];
__device__ float g_d1[N_EDGES];
__device__ float g_vals_n[NNZ];
__device__ float g_vals_t[NNZ];
__device__ int   g_counts[N_NODES];
__device__ int   g_offs[N_NODES];
__device__ int   g_cursor[N_NODES];
__device__ int   g_ecounts[N_EDGES];
__device__ int   g_eoffs[N_EDGES];
__device__ int   g_csr[NNZ];
__device__ int   g_bsum_n[128];
__device__ int   g_bsum_e[128];
__device__ float g_agg[N_EDGES * HID];
__device__ float g_x1 [N_EDGES * HID];
__device__ float g_M1 [N_EDGES * HID];
__device__ float g_x0 [N_NODES * HID];
__device__ float g_pooled[HID];

// ---------------- small init ------------------------------------------------
__global__ void k_zero_small() {
    int i = blockIdx.x * blockDim.x + threadIdx.x;
    if (i < N_NODES) { g_node_sum[i] = 0.f; g_d0[i] = 0.f; g_counts[i] = 0; g_cursor[i] = 0; }
    if (i < N_EDGES) { g_edge_sum[i] = 0.f; g_d1[i] = 0.f; g_ecounts[i] = 0; }
    if (i < HID)     { g_pooled[i] = 0.f; }
}

// ---------------- normalization ----------------------------------------------
__global__ void k_seg_sums(const float* __restrict__ vals, const int* __restrict__ rows,
                           const int* __restrict__ cols) {
    int k = blockIdx.x * blockDim.x + threadIdx.x;
    if (k >= NNZ) return;
    float v = vals[k];
    atomicAdd(&g_edge_sum[cols[k]], v);
    atomicAdd(&g_node_sum[rows[k]], v);
}

__global__ void k_cards() {
    int i = blockIdx.x * blockDim.x + threadIdx.x;
    if (i < N_NODES) g_node_card[i] = powf(g_node_sum[i], -0.5f);
    if (i < N_EDGES) g_edge_card[i] = powf(g_edge_sum[i], -1.5f);
}

__global__ void k_dsums(const float* __restrict__ vals, const int* __restrict__ rows,
                        const int* __restrict__ cols) {
    int k = blockIdx.x * blockDim.x + threadIdx.x;
    if (k >= NNZ) return;
    float nz = (vals[k] != 0.f) ? 1.f : 0.f;
    atomicAdd(&g_d0[rows[k]], g_edge_card[cols[k]] * nz);
    atomicAdd(&g_d1[cols[k]], g_node_card[rows[k]] * nz);
}

__global__ void k_valsnt(const float* __restrict__ vals, const int* __restrict__ rows,
                         const int* __restrict__ cols) {
    int k = blockIdx.x * blockDim.x + threadIdx.x;
    if (k >= NNZ) return;
    int r = rows[k], c = cols[k];
    float v = vals[k];
    g_vals_n[k] = v * g_edge_card[c] / g_d0[r];
    g_vals_t[k] = v * g_node_card[r] / g_d1[c];
    atomicAdd(&g_counts[r], 1);    // node degrees (row-CSR)
    atomicAdd(&g_ecounts[c], 1);   // edge cardinalities (range lookup)
}

// ---------------- generic exclusive scan (two-level) -------------------------
__global__ void k_scanA_g(const int* __restrict__ in, int* __restrict__ out,
                          int* __restrict__ bsum, int n) {
    __shared__ int sh[1024];
    int b = blockIdx.x, t = threadIdx.x;
    int i = b * 1024 + t;
    int v = (i < n) ? in[i] : 0;
    sh[t] = v;
    __syncthreads();
    for (int d = 1; d < 1024; d <<= 1) {
        int add = (t >= d) ? sh[t - d] : 0;
        __syncthreads();
        sh[t] += add;
        __syncthreads();
    }
    if (i < n) out[i] = sh[t] - v;   // exclusive
    if (t == 1023) bsum[b] = sh[t];
}

__global__ void k_scanB_g(int* __restrict__ bsum, int nb) {
    if (threadIdx.x == 0) {
        int acc = 0;
        for (int i = 0; i < nb; i++) { int t = bsum[i]; bsum[i] = acc; acc += t; }
    }
}

__global__ void k_scanC_g(int* __restrict__ out, const int* __restrict__ bsum, int n) {
    int i = blockIdx.x * blockDim.x + threadIdx.x;
    if (i < n) out[i] += bsum[i >> 10];
}

__global__ void k_fill_csr(const int* __restrict__ rows) {
    int k = blockIdx.x * blockDim.x + threadIdx.x;
    if (k >= NNZ) return;
    int v = rows[k];
    int p = g_offs[v] + atomicAdd(&g_cursor[v], 1);
    g_csr[p] = k;
}

// ---------------- node -> edge aggregation via edge offsets ------------------
// dim = 64 scalar version (layer 0 input)
__global__ void k_agg_edges64(const float* __restrict__ x, const int* __restrict__ rows) {
    int e = blockIdx.x;
    int c = threadIdx.x;   // 0..63
    int lo = g_eoffs[e];
    int hi = lo + g_ecounts[e];
    float acc = 0.f;
    for (int k = lo; k < hi; k++)
        acc += g_vals_t[k] * x[rows[k] * IN_CH + c];
    g_agg[e * IN_CH + c] = acc;
}

// dim = 256 float4 version (layer 1)
__global__ void k_agg_edges256(const float* __restrict__ x, const int* __restrict__ rows) {
    int e = blockIdx.x;
    int c = threadIdx.x;   // 0..63 -> float4 lane
    int lo = g_eoffs[e];
    int hi = lo + g_ecounts[e];
    float4 acc = make_float4(0.f, 0.f, 0.f, 0.f);
    for (int k = lo; k < hi; k++) {
        float vt = g_vals_t[k];
        const float4* xr = reinterpret_cast<const float4*>(&x[rows[k] * HID]);
        float4 v = xr[c];
        acc.x += vt * v.x; acc.y += vt * v.y; acc.z += vt * v.z; acc.w += vt * v.w;
    }
    reinterpret_cast<float4*>(&g_agg[e * HID])[c] = acc;
}

// ---------------- TF32 tensor-core GEMM: C = A(MxK) @ B(Kx256) ---------------
// BM=128, BN=128, BK=32. 8 warps (4M x 2N), warp tile 32x64 via m16n8k8.
// Register-prefetch double buffering over a single smem buffer.
__device__ __forceinline__ uint32_t f2tf32(float f) {
    uint32_t u;
    asm("cvt.rna.tf32.f32 %0, %1;" : "=r"(u) : "f"(f));
    return u;
}

__device__ __forceinline__ void mma_tf32(float c[4],
                                         uint32_t a0, uint32_t a1, uint32_t a2, uint32_t a3,
                                         uint32_t b0, uint32_t b1) {
    asm volatile(
        "mma.sync.aligned.m16n8k8.row.col.f32.tf32.tf32.f32 "
        "{%0,%1,%2,%3}, {%4,%5,%6,%7}, {%8,%9}, {%0,%1,%2,%3};\n"
        : "+f"(c[0]), "+f"(c[1]), "+f"(c[2]), "+f"(c[3])
        : "r"(a0), "r"(a1), "r"(a2), "r"(a3), "r"(b0), "r"(b1));
}

#define AS_STRIDE 36    // banks (4g + tig) unique
#define BS_STRIDE 136   // banks (8tig + g) unique

__global__ __launch_bounds__(256, 1)
void k_mma_gemm(const float* __restrict__ A, const float* __restrict__ B,
                const float* __restrict__ bias, float* __restrict__ C,
                int M, int K, int relu) {
    __shared__ uint32_t As[128 * AS_STRIDE];
    __shared__ uint32_t Bs[32 * BS_STRIDE];
    const int N = HID;
    int tid = threadIdx.x;
    int lane = tid & 31, wid = tid >> 5;
    int wm = wid & 3, wn = wid >> 2;          // warps: 4 in M x 2 in N
    int g = lane >> 2, tig = lane & 3;        // groupID, threadInGroup
    int bm = blockIdx.y * 128, bn = blockIdx.x * 128;

    float acc[2][8][4];
    #pragma unroll
    for (int mi = 0; mi < 2; mi++)
        #pragma unroll
        for (int ni = 0; ni < 8; ni++)
            #pragma unroll
            for (int r = 0; r < 4; r++) acc[mi][ni][r] = 0.f;

    // per-thread staging slots: A 4x float4, B 4x float4
    float4 pa[4], pb[4];

    // ---- load tile 0 into regs ----
    #pragma unroll
    for (int j = 0; j < 4; j++) {
        int i = tid + j * 256;
        int m = i >> 3, k4 = (i & 7) << 2;
        pa[j] = make_float4(0.f, 0.f, 0.f, 0.f);
        if (bm + m < M)
            pa[j] = *reinterpret_cast<const float4*>(&A[(size_t)(bm + m) * K + k4]);
    }
    #pragma unroll
    for (int j = 0; j < 4; j++) {
        int i = tid + j * 256;
        int k = i >> 5, n4 = (i & 31) << 2;
        pb[j] = *reinterpret_cast<const float4*>(&B[(size_t)k * N + bn + n4]);
    }

    for (int k0 = 0; k0 < K; k0 += 32) {
        // store staged regs -> smem (tf32 convert)
        #pragma unroll
        for (int j = 0; j < 4; j++) {
            int i = tid + j * 256;
            int m = i >> 3, k4 = (i & 7) << 2;
            uint4 u = make_uint4(f2tf32(pa[j].x), f2tf32(pa[j].y),
                                 f2tf32(pa[j].z), f2tf32(pa[j].w));
            *reinterpret_cast<uint4*>(&As[m * AS_STRIDE + k4]) = u;
        }
        #pragma unroll
        for (int j = 0; j < 4; j++) {
            int i = tid + j * 256;
            int k = i >> 5, n4 = (i & 31) << 2;
            uint4 u = make_uint4(f2tf32(pb[j].x), f2tf32(pb[j].y),
                                 f2tf32(pb[j].z), f2tf32(pb[j].w));
            *reinterpret_cast<uint4*>(&Bs[k * BS_STRIDE + n4]) = u;
        }
        __syncthreads();

        // prefetch next tile into regs while computing this one
        int kn = k0 + 32;
        if (kn < K) {
            #pragma unroll
            for (int j = 0; j < 4; j++) {
                int i = tid + j * 256;
                int m = i >> 3, k4 = (i & 7) << 2;
                pa[j] = make_float4(0.f, 0.f, 0.f, 0.f);
                if (bm + m < M)
                    pa[j] = *reinterpret_cast<const float4*>(&A[(size_t)(bm + m) * K + kn + k4]);
            }
            #pragma unroll
            for (int j = 0; j < 4; j++) {
                int i = tid + j * 256;
                int k = i >> 5, n4 = (i & 31) << 2;
                pb[j] = *reinterpret_cast<const float4*>(&B[(size_t)(kn + k) * N + bn + n4]);
            }
        }

        #pragma unroll
        for (int ks = 0; ks < 32; ks += 8) {
            uint32_t a[2][4], b[8][2];
            #pragma unroll
            for (int mi = 0; mi < 2; mi++) {
                int mrow = wm * 32 + mi * 16 + g;
                a[mi][0] = As[(mrow    ) * AS_STRIDE + ks + tig];
                a[mi][1] = As[(mrow + 8) * AS_STRIDE + ks + tig];
                a[mi][2] = As[(mrow    ) * AS_STRIDE + ks + tig + 4];
                a[mi][3] = As[(mrow + 8) * AS_STRIDE + ks + tig + 4];
            }
            #pragma unroll
            for (int ni = 0; ni < 8; ni++) {
                int ncol = wn * 64 + ni * 8 + g;
                b[ni][0] = Bs[(ks + tig    ) * BS_STRIDE + ncol];
                b[ni][1] = Bs[(ks + tig + 4) * BS_STRIDE + ncol];
            }
            #pragma unroll
            for (int mi = 0; mi < 2; mi++)
                #pragma unroll
                for (int ni = 0; ni < 8; ni++)
                    mma_tf32(acc[mi][ni], a[mi][0], a[mi][1], a[mi][2], a[mi][3],
                             b[ni][0], b[ni][1]);
        }
        __syncthreads();
    }

    // epilogue
    #pragma unroll
    for (int mi = 0; mi < 2; mi++) {
        #pragma unroll
        for (int ni = 0; ni < 8; ni++) {
            int row0 = bm + wm * 32 + mi * 16 + g;
            int col0 = bn + wn * 64 + ni * 8 + 2 * tig;
            float bv0 = bias ? bias[col0]     : 0.f;
            float bv1 = bias ? bias[col0 + 1] : 0.f;
            float v00 = acc[mi][ni][0] + bv0;
            float v01 = acc[mi][ni][1] + bv1;
            float v10 = acc[mi][ni][2] + bv0;
            float v11 = acc[mi][ni][3] + bv1;
            if (relu) {
                v00 = fmaxf(v00, 0.f); v01 = fmaxf(v01, 0.f);
                v10 = fmaxf(v10, 0.f); v11 = fmaxf(v11, 0.f);
            }
            if (row0 < M)
                *reinterpret_cast<float2*>(&C[(size_t)row0 * N + col0]) = make_float2(v00, v01);
            if (row0 + 8 < M)
                *reinterpret_cast<float2*>(&C[(size_t)(row0 + 8) * N + col0]) = make_float2(v10, v11);
        }
    }
}

// ---------------- edge -> node gather via row-CSR (+bias, relu), float4 ------
__global__ void k_gather_nodes(const float* __restrict__ b0, const int* __restrict__ cols) {
    int v = blockIdx.x;
    int c = threadIdx.x;   // 0..63 float4 lane
    int off = g_offs[v];
    int n   = g_counts[v];
    float4 acc = reinterpret_cast<const float4*>(b0)[c];
    for (int j = 0; j < n; j++) {
        int k = g_csr[off + j];
        float vn = g_vals_n[k];
        float4 m = reinterpret_cast<const float4*>(&g_M1[cols[k] * HID])[c];
        acc.x += vn * m.x; acc.y += vn * m.y; acc.z += vn * m.z; acc.w += vn * m.w;
    }
    acc.x = fmaxf(acc.x, 0.f); acc.y = fmaxf(acc.y, 0.f);
    acc.z = fmaxf(acc.z, 0.f); acc.w = fmaxf(acc.w, 0.f);
    reinterpret_cast<float4*>(&g_x0[v * HID])[c] = acc;
}

// ---------------- max pool over nodes + final dot ----------------------------
__global__ void k_maxpool() {
    int c = threadIdx.x;
    int rb = blockIdx.x;
    const int RPB = (N_NODES + 399) / 400;
    int r0 = rb * RPB;
    int r1 = min(r0 + RPB, N_NODES);
    float m = 0.f;   // relu outputs are >= 0
    for (int r = r0; r < r1; r++)
        m = fmaxf(m, g_x0[r * HID + c]);
    atomicMax((int*)&g_pooled[c], __float_as_int(m));   // valid for nonneg floats
}

__global__ void k_final(const float* __restrict__ lin_w, const float* __restrict__ lin_b,
                        float* __restrict__ out) {
    __shared__ float sh[256];
    int c = threadIdx.x;
    sh[c] = g_pooled[c] * lin_w[c];
    __syncthreads();
    for (int s = 128; s > 0; s >>= 1) {
        if (c < s) sh[c] += sh[c + s];
        __syncthreads();
    }
    if (c == 0) out[0] = sh[0] + lin_b[0];
}

// ---------------- launch ------------------------------------------------------
extern "C" void kernel_launch(void* const* d_in, const int* in_sizes, int n_in,
                              void* d_out, int out_size) {
    const float* x_in  = (const float*)d_in[0];
    const float* vals  = (const float*)d_in[1];
    const int*   rows  = (const int*)  d_in[2];
    const int*   cols  = (const int*)  d_in[3];
    const float* W0_l0 = (const float*)d_in[4];
    const float* W1_l0 = (const float*)d_in[5];
    const float* b1_l0 = (const float*)d_in[6];
    const float* b0_l0 = (const float*)d_in[7];
    const float* W0_l1 = (const float*)d_in[8];
    const float* W1_l1 = (const float*)d_in[9];
    const float* b1_l1 = (const float*)d_in[10];
    const float* b0_l1 = (const float*)d_in[11];
    const float* lin_w = (const float*)d_in[12];
    const float* lin_b = (const float*)d_in[13];
    float* out = (float*)d_out;

    float *p_agg, *p_x1, *p_M1, *p_x0;
    int *p_counts, *p_offs, *p_ecounts, *p_eoffs, *p_bsum_n, *p_bsum_e;
    cudaGetSymbolAddress((void**)&p_agg, g_agg);
    cudaGetSymbolAddress((void**)&p_x1,  g_x1);
    cudaGetSymbolAddress((void**)&p_M1,  g_M1);
    cudaGetSymbolAddress((void**)&p_x0,  g_x0);
    cudaGetSymbolAddress((void**)&p_counts,  g_counts);
    cudaGetSymbolAddress((void**)&p_offs,    g_offs);
    cudaGetSymbolAddress((void**)&p_ecounts, g_ecounts);
    cudaGetSymbolAddress((void**)&p_eoffs,   g_eoffs);
    cudaGetSymbolAddress((void**)&p_bsum_n,  g_bsum_n);
    cudaGetSymbolAddress((void**)&p_bsum_e,  g_bsum_e);

    const int TB = 256;
    const int gN = (N_NODES + TB - 1) / TB;
    const int gZ = (NNZ + TB - 1) / TB;
    const int NBLK_N = (N_NODES + 1023) / 1024;
    const int NBLK_E = (N_EDGES + 1023) / 1024;

    // normalization + offsets/CSR build
    k_zero_small<<<gN, TB>>>();
    k_seg_sums<<<gZ, TB>>>(vals, rows, cols);
    k_cards<<<gN, TB>>>();
    k_dsums<<<gZ, TB>>>(vals, rows, cols);
    k_valsnt<<<gZ, TB>>>(vals, rows, cols);
    // node offsets (for CSR) and edge offsets (for range lookup)
    k_scanA_g<<<NBLK_N, 1024>>>(p_counts, p_offs, p_bsum_n, N_NODES);
    k_scanA_g<<<NBLK_E, 1024>>>(p_ecounts, p_eoffs, p_bsum_e, N_EDGES);
    k_scanB_g<<<1, 32>>>(p_bsum_n, NBLK_N);
    k_scanB_g<<<1, 32>>>(p_bsum_e, NBLK_E);
    k_scanC_g<<<gN, TB>>>(p_offs, p_bsum_n, N_NODES);
    k_scanC_g<<<(N_EDGES + TB - 1) / TB, TB>>>(p_eoffs, p_bsum_e, N_EDGES);
    k_fill_csr<<<gZ, TB>>>(rows);

    dim3 gemm_grid(HID / 128, (N_EDGES + 127) / 128);

    // ---- layer 0 ----
    k_agg_edges64<<<N_EDGES, IN_CH>>>(x_in, rows);
    k_mma_gemm<<<gemm_grid, 256>>>(p_agg, W0_l0, b1_l0, p_x1, N_EDGES, IN_CH, 1);
    k_mma_gemm<<<gemm_grid, 256>>>(p_x1, W1_l0, nullptr, p_M1, N_EDGES, HID, 0);
    k_gather_nodes<<<N_NODES, 64>>>(b0_l0, cols);

    // ---- layer 1 ----
    k_agg_edges256<<<N_EDGES, 64>>>(p_x0, rows);
    k_mma_gemm<<<gemm_grid, 256>>>(p_agg, W0_l1, b1_l1, p_x1, N_EDGES, HID, 1);
    k_mma_gemm<<<gemm_grid, 256>>>(p_x1, W1_l1, nullptr, p_M1, N_EDGES, HID, 0);
    k_gather_nodes<<<N_NODES, 64>>>(b0_l1, cols);

    // ---- pool + head ----
    k_maxpool<<<400, HID>>>();
    k_final<<<1, HID>>>(lin_w, lin_b, out);
}

// round 5
// speedup vs baseline: 3.6090x; 1.1876x over previous
#include <cuda_runtime.h>
#include <cuda_fp16.h>
#include <math.h>
#include <stdint.h>

// ---------------- problem constants ------------------------------------------
#define N_NODES 100000
#define N_EDGES 50000
#define NNZ     400000
#define IN_CH   64
#define HID     256

// ---------------- device scratch ----------------------------------------------
__device__ float g_edge_sum[N_EDGES];
__device__ float g_node_sum[N_NODES];
__device__ float g_edge_card[N_EDGES];
__device__ float g_node_card[N_NODES];
__device__ float g_d0[N_NODES];
__device__ float g_d1[N_EDGES];
__device__ float g_vals_n[NNZ];
__device__ float g_vals_t[NNZ];
__device__ int   g_counts[N_NODES];
__device__ int   g_offs[N_NODES];
__device__ int   g_cursor[N_NODES];
__device__ int   g_ecounts[N_EDGES];
__device__ int   g_eoffs[N_EDGES];
__device__ int   g_csr[NNZ];
__device__ int   g_bsum_n[128];
__device__ int   g_bsum_e[128];
__device__ __align__(16) __half g_agg_h[N_EDGES * HID];   // GEMM1 input (half)
__device__ __align__(16) __half g_x1h  [N_EDGES * HID];   // GEMM1 output / GEMM2 input
__device__ float g_M1 [N_EDGES * HID];                    // GEMM2 output (float)
__device__ float g_x0 [N_NODES * HID];
__device__ float g_pooled[HID];
// pre-transposed half weights: [N=HID rows, K cols] row-major
__device__ __align__(16) __half g_W0t0h[HID * IN_CH];
__device__ __align__(16) __half g_W1t0h[HID * HID];
__device__ __align__(16) __half g_W0t1h[HID * HID];
__device__ __align__(16) __half g_W1t1h[HID * HID];

// ---------------- small init ---------------------------------------------------
__global__ void k_zero_small() {
    int i = blockIdx.x * blockDim.x + threadIdx.x;
    if (i < N_NODES) { g_node_sum[i] = 0.f; g_d0[i] = 0.f; g_counts[i] = 0; g_cursor[i] = 0; }
    if (i < N_EDGES) { g_edge_sum[i] = 0.f; g_d1[i] = 0.f; g_ecounts[i] = 0; }
    if (i < HID)     { g_pooled[i] = 0.f; }
}

// ---------------- normalization ------------------------------------------------
__global__ void k_seg_sums(const float* __restrict__ vals, const int* __restrict__ rows,
                           const int* __restrict__ cols) {
    int k = blockIdx.x * blockDim.x + threadIdx.x;
    if (k >= NNZ) return;
    float v = vals[k];
    atomicAdd(&g_edge_sum[cols[k]], v);
    atomicAdd(&g_node_sum[rows[k]], v);
}

__global__ void k_cards() {
    int i = blockIdx.x * blockDim.x + threadIdx.x;
    if (i < N_NODES) g_node_card[i] = powf(g_node_sum[i], -0.5f);
    if (i < N_EDGES) g_edge_card[i] = powf(g_edge_sum[i], -1.5f);
}

__global__ void k_dsums(const float* __restrict__ vals, const int* __restrict__ rows,
                        const int* __restrict__ cols) {
    int k = blockIdx.x * blockDim.x + threadIdx.x;
    if (k >= NNZ) return;
    float nz = (vals[k] != 0.f) ? 1.f : 0.f;
    atomicAdd(&g_d0[rows[k]], g_edge_card[cols[k]] * nz);
    atomicAdd(&g_d1[cols[k]], g_node_card[rows[k]] * nz);
}

__global__ void k_valsnt(const float* __restrict__ vals, const int* __restrict__ rows,
                         const int* __restrict__ cols) {
    int k = blockIdx.x * blockDim.x + threadIdx.x;
    if (k >= NNZ) return;
    int r = rows[k], c = cols[k];
    float v = vals[k];
    g_vals_n[k] = v * g_edge_card[c] / g_d0[r];
    g_vals_t[k] = v * g_node_card[r] / g_d1[c];
    atomicAdd(&g_counts[r], 1);
    atomicAdd(&g_ecounts[c], 1);
}

// ---------------- generic exclusive scan (two-level) ---------------------------
__global__ void k_scanA_g(const int* __restrict__ in, int* __restrict__ out,
                          int* __restrict__ bsum, int n) {
    __shared__ int sh[1024];
    int b = blockIdx.x, t = threadIdx.x;
    int i = b * 1024 + t;
    int v = (i < n) ? in[i] : 0;
    sh[t] = v;
    __syncthreads();
    for (int d = 1; d < 1024; d <<= 1) {
        int add = (t >= d) ? sh[t - d] : 0;
        __syncthreads();
        sh[t] += add;
        __syncthreads();
    }
    if (i < n) out[i] = sh[t] - v;
    if (t == 1023) bsum[b] = sh[t];
}

__global__ void k_scanB_g(int* __restrict__ bsum, int nb) {
    if (threadIdx.x == 0) {
        int acc = 0;
        for (int i = 0; i < nb; i++) { int t = bsum[i]; bsum[i] = acc; acc += t; }
    }
}

__global__ void k_scanC_g(int* __restrict__ out, const int* __restrict__ bsum, int n) {
    int i = blockIdx.x * blockDim.x + threadIdx.x;
    if (i < n) out[i] += bsum[i >> 10];
}

__global__ void k_fill_csr(const int* __restrict__ rows) {
    int k = blockIdx.x * blockDim.x + threadIdx.x;
    if (k >= NNZ) return;
    int v = rows[k];
    int p = g_offs[v] + atomicAdd(&g_cursor[v], 1);
    g_csr[p] = k;
}

// ---------------- weight transpose+convert: dst[n*K+k] = half(src[k*N+n]) -----
__global__ void k_transpose_h(__half* __restrict__ dst, const float* __restrict__ src,
                              int K, int N) {
    int i = blockIdx.x * blockDim.x + threadIdx.x;
    if (i >= K * N) return;
    int k = i / N, n = i % N;
    dst[n * K + k] = __float2half(src[i]);
}

// ---------------- node -> edge aggregation (outputs half) ----------------------
__global__ void k_agg_edges64(const float* __restrict__ x, const int* __restrict__ rows) {
    int e = blockIdx.x;
    int c = threadIdx.x;   // 0..63
    int lo = g_eoffs[e];
    int hi = lo + g_ecounts[e];
    float acc = 0.f;
    for (int k = lo; k < hi; k++)
        acc += g_vals_t[k] * x[rows[k] * IN_CH + c];
    g_agg_h[e * IN_CH + c] = __float2half(acc);
}

__global__ void k_agg_edges256(const float* __restrict__ x, const int* __restrict__ rows) {
    int e = blockIdx.x;
    int c = threadIdx.x;   // 0..63 -> float4 lane
    int lo = g_eoffs[e];
    int hi = lo + g_ecounts[e];
    float4 acc = make_float4(0.f, 0.f, 0.f, 0.f);
    for (int k = lo; k < hi; k++) {
        float vt = g_vals_t[k];
        const float4* xr = reinterpret_cast<const float4*>(&x[rows[k] * HID]);
        float4 v = xr[c];
        acc.x += vt * v.x; acc.y += vt * v.y; acc.z += vt * v.z; acc.w += vt * v.w;
    }
    __half2 h0 = __floats2half2_rn(acc.x, acc.y);
    __half2 h1 = __floats2half2_rn(acc.z, acc.w);
    uint2 u = make_uint2(*reinterpret_cast<uint32_t*>(&h0), *reinterpret_cast<uint32_t*>(&h1));
    *reinterpret_cast<uint2*>(&g_agg_h[e * HID + c * 4]) = u;
}

// ---------------- fp16 tensor-core GEMM ----------------------------------------
// C = A(MxK, half) @ Bt(256xK, half)^T ; BM=128, BN=128, BK=32.
// 8 warps (4M x 2N), warp tile 32x64 via m16n8k16. Reg-prefetch double buffer.
// OUT_HALF: C half with bias+relu. else: C float plain.

__device__ __forceinline__ void mma_f16(float c[4], uint32_t a0, uint32_t a1,
                                        uint32_t a2, uint32_t a3,
                                        uint32_t b0, uint32_t b1) {
    asm volatile(
        "mma.sync.aligned.m16n8k16.row.col.f32.f16.f16.f32 "
        "{%0,%1,%2,%3}, {%4,%5,%6,%7}, {%8,%9}, {%0,%1,%2,%3};\n"
        : "+f"(c[0]), "+f"(c[1]), "+f"(c[2]), "+f"(c[3])
        : "r"(a0), "r"(a1), "r"(a2), "r"(a3), "r"(b0), "r"(b1));
}

#define HS_STRIDE 40   // halfs; bank = 20m+tig mod 32, unique over 8x4 lanes

template <int OUT_HALF>
__global__ __launch_bounds__(256)
void k_gemm_f16(const __half* __restrict__ A, const __half* __restrict__ Bt,
                const float* __restrict__ bias, void* __restrict__ Cout,
                int M, int K) {
    __shared__ __half As[128 * HS_STRIDE];
    __shared__ __half Bs[128 * HS_STRIDE];
    const int N = HID;
    int tid = threadIdx.x;
    int lane = tid & 31, wid = tid >> 5;
    int wm = wid & 3, wn = wid >> 2;
    int g = lane >> 2, tig = lane & 3;
    int bm = blockIdx.y * 128, bn = blockIdx.x * 128;

    float acc[2][8][4];
    #pragma unroll
    for (int mi = 0; mi < 2; mi++)
        #pragma unroll
        for (int ni = 0; ni < 8; ni++)
            #pragma unroll
            for (int r = 0; r < 4; r++) acc[mi][ni][r] = 0.f;

    // staging: each thread owns 16 halfs of A and 16 of B per chunk
    int sm = tid >> 1;              // row 0..127
    int skh = (tid & 1) * 16;       // k offset 0 or 16
    uint4 pa0, pa1, pb0, pb1;

    // load chunk 0
    {
        const __half* Ap = A + (size_t)(bm + sm) * K + skh;
        if (bm + sm < M) {
            pa0 = *reinterpret_cast<const uint4*>(Ap);
            pa1 = *reinterpret_cast<const uint4*>(Ap + 8);
        } else {
            pa0 = make_uint4(0, 0, 0, 0); pa1 = pa0;
        }
        const __half* Bp = Bt + (size_t)(bn + sm) * K + skh;
        pb0 = *reinterpret_cast<const uint4*>(Bp);
        pb1 = *reinterpret_cast<const uint4*>(Bp + 8);
    }

    for (int k0 = 0; k0 < K; k0 += 32) {
        // store staged regs -> smem
        *reinterpret_cast<uint4*>(&As[sm * HS_STRIDE + skh])     = pa0;
        *reinterpret_cast<uint4*>(&As[sm * HS_STRIDE + skh + 8]) = pa1;
        *reinterpret_cast<uint4*>(&Bs[sm * HS_STRIDE + skh])     = pb0;
        *reinterpret_cast<uint4*>(&Bs[sm * HS_STRIDE + skh + 8]) = pb1;
        __syncthreads();

        // prefetch next chunk
        int kn = k0 + 32;
        if (kn < K) {
            const __half* Ap = A + (size_t)(bm + sm) * K + kn + skh;
            if (bm + sm < M) {
                pa0 = *reinterpret_cast<const uint4*>(Ap);
                pa1 = *reinterpret_cast<const uint4*>(Ap + 8);
            } else {
                pa0 = make_uint4(0, 0, 0, 0); pa1 = pa0;
            }
            const __half* Bp = Bt + (size_t)(bn + sm) * K + kn + skh;
            pb0 = *reinterpret_cast<const uint4*>(Bp);
            pb1 = *reinterpret_cast<const uint4*>(Bp + 8);
        }

        #pragma unroll
        for (int ks = 0; ks < 32; ks += 16) {
            uint32_t a[2][4], b[8][2];
            #pragma unroll
            for (int mi = 0; mi < 2; mi++) {
                int mrow = wm * 32 + mi * 16 + g;
                a[mi][0] = *reinterpret_cast<const uint32_t*>(&As[(mrow    ) * HS_STRIDE + ks + 2 * tig]);
                a[mi][1] = *reinterpret_cast<const uint32_t*>(&As[(mrow + 8) * HS_STRIDE + ks + 2 * tig]);
                a[mi][2] = *reinterpret_cast<const uint32_t*>(&As[(mrow    ) * HS_STRIDE + ks + 2 * tig + 8]);
                a[mi][3] = *reinterpret_cast<const uint32_t*>(&As[(mrow + 8) * HS_STRIDE + ks + 2 * tig + 8]);
            }
            #pragma unroll
            for (int ni = 0; ni < 8; ni++) {
                int ncol = wn * 64 + ni * 8 + g;
                b[ni][0] = *reinterpret_cast<const uint32_t*>(&Bs[ncol * HS_STRIDE + ks + 2 * tig]);
                b[ni][1] = *reinterpret_cast<const uint32_t*>(&Bs[ncol * HS_STRIDE + ks + 2 * tig + 8]);
            }
            #pragma unroll
            for (int mi = 0; mi < 2; mi++)
                #pragma unroll
                for (int ni = 0; ni < 8; ni++)
                    mma_f16(acc[mi][ni], a[mi][0], a[mi][1], a[mi][2], a[mi][3],
                            b[ni][0], b[ni][1]);
        }
        __syncthreads();
    }

    // epilogue
    #pragma unroll
    for (int mi = 0; mi < 2; mi++) {
        #pragma unroll
        for (int ni = 0; ni < 8; ni++) {
            int row0 = bm + wm * 32 + mi * 16 + g;
            int col0 = bn + wn * 64 + ni * 8 + 2 * tig;
            if (OUT_HALF) {
                float bv0 = bias[col0], bv1 = bias[col0 + 1];
                __half2 h0 = __floats2half2_rn(fmaxf(acc[mi][ni][0] + bv0, 0.f),
                                               fmaxf(acc[mi][ni][1] + bv1, 0.f));
                __half2 h1 = __floats2half2_rn(fmaxf(acc[mi][ni][2] + bv0, 0.f),
                                               fmaxf(acc[mi][ni][3] + bv1, 0.f));
                __half* C = (__half*)Cout;
                if (row0 < M)
                    *reinterpret_cast<__half2*>(&C[(size_t)row0 * N + col0]) = h0;
                if (row0 + 8 < M)
                    *reinterpret_cast<__half2*>(&C[(size_t)(row0 + 8) * N + col0]) = h1;
            } else {
                float* C = (float*)Cout;
                if (row0 < M)
                    *reinterpret_cast<float2*>(&C[(size_t)row0 * N + col0]) =
                        make_float2(acc[mi][ni][0], acc[mi][ni][1]);
                if (row0 + 8 < M)
                    *reinterpret_cast<float2*>(&C[(size_t)(row0 + 8) * N + col0]) =
                        make_float2(acc[mi][ni][2], acc[mi][ni][3]);
            }
        }
    }
}

// ---------------- edge -> node gather via row-CSR (+bias, relu), float4 --------
__global__ void k_gather_nodes(const float* __restrict__ b0, const int* __restrict__ cols) {
    int v = blockIdx.x;
    int c = threadIdx.x;
    int off = g_offs[v];
    int n   = g_counts[v];
    float4 acc = reinterpret_cast<const float4*>(b0)[c];
    for (int j = 0; j < n; j++) {
        int k = g_csr[off + j];
        float vn = g_vals_n[k];
        float4 m = reinterpret_cast<const float4*>(&g_M1[cols[k] * HID])[c];
        acc.x += vn * m.x; acc.y += vn * m.y; acc.z += vn * m.z; acc.w += vn * m.w;
    }
    acc.x = fmaxf(acc.x, 0.f); acc.y = fmaxf(acc.y, 0.f);
    acc.z = fmaxf(acc.z, 0.f); acc.w = fmaxf(acc.w, 0.f);
    reinterpret_cast<float4*>(&g_x0[v * HID])[c] = acc;
}

// ---------------- max pool over nodes + final dot -------------------------------
__global__ void k_maxpool() {
    int c = threadIdx.x;
    int rb = blockIdx.x;
    const int RPB = (N_NODES + 399) / 400;
    int r0 = rb * RPB;
    int r1 = min(r0 + RPB, N_NODES);
    float m = 0.f;
    for (int r = r0; r < r1; r++)
        m = fmaxf(m, g_x0[r * HID + c]);
    atomicMax((int*)&g_pooled[c], __float_as_int(m));
}

__global__ void k_final(const float* __restrict__ lin_w, const float* __restrict__ lin_b,
                        float* __restrict__ out) {
    __shared__ float sh[256];
    int c = threadIdx.x;
    sh[c] = g_pooled[c] * lin_w[c];
    __syncthreads();
    for (int s = 128; s > 0; s >>= 1) {
        if (c < s) sh[c] += sh[c + s];
        __syncthreads();
    }
    if (c == 0) out[0] = sh[0] + lin_b[0];
}

// ---------------- launch ---------------------------------------------------------
extern "C" void kernel_launch(void* const* d_in, const int* in_sizes, int n_in,
                              void* d_out, int out_size) {
    const float* x_in  = (const float*)d_in[0];
    const float* vals  = (const float*)d_in[1];
    const int*   rows  = (const int*)  d_in[2];
    const int*   cols  = (const int*)  d_in[3];
    const float* W0_l0 = (const float*)d_in[4];
    const float* W1_l0 = (const float*)d_in[5];
    const float* b1_l0 = (const float*)d_in[6];
    const float* b0_l0 = (const float*)d_in[7];
    const float* W0_l1 = (const float*)d_in[8];
    const float* W1_l1 = (const float*)d_in[9];
    const float* b1_l1 = (const float*)d_in[10];
    const float* b0_l1 = (const float*)d_in[11];
    const float* lin_w = (const float*)d_in[12];
    const float* lin_b = (const float*)d_in[13];
    float* out = (float*)d_out;

    __half *p_agg_h, *p_x1h, *p_W0t0h, *p_W1t0h, *p_W0t1h, *p_W1t1h;
    float *p_M1, *p_x0;
    int *p_counts, *p_offs, *p_ecounts, *p_eoffs, *p_bsum_n, *p_bsum_e;
    cudaGetSymbolAddress((void**)&p_agg_h, g_agg_h);
    cudaGetSymbolAddress((void**)&p_x1h,   g_x1h);
    cudaGetSymbolAddress((void**)&p_M1,    g_M1);
    cudaGetSymbolAddress((void**)&p_x0,    g_x0);
    cudaGetSymbolAddress((void**)&p_W0t0h, g_W0t0h);
    cudaGetSymbolAddress((void**)&p_W1t0h, g_W1t0h);
    cudaGetSymbolAddress((void**)&p_W0t1h, g_W0t1h);
    cudaGetSymbolAddress((void**)&p_W1t1h, g_W1t1h);
    cudaGetSymbolAddress((void**)&p_counts,  g_counts);
    cudaGetSymbolAddress((void**)&p_offs,    g_offs);
    cudaGetSymbolAddress((void**)&p_ecounts, g_ecounts);
    cudaGetSymbolAddress((void**)&p_eoffs,   g_eoffs);
    cudaGetSymbolAddress((void**)&p_bsum_n,  g_bsum_n);
    cudaGetSymbolAddress((void**)&p_bsum_e,  g_bsum_e);

    const int TB = 256;
    const int gN = (N_NODES + TB - 1) / TB;
    const int gZ = (NNZ + TB - 1) / TB;
    const int NBLK_N = (N_NODES + 1023) / 1024;
    const int NBLK_E = (N_EDGES + 1023) / 1024;

    // weight transposes + convert to half
    k_transpose_h<<<(IN_CH * HID + TB - 1) / TB, TB>>>(p_W0t0h, W0_l0, IN_CH, HID);
    k_transpose_h<<<(HID * HID + TB - 1) / TB, TB>>>(p_W1t0h, W1_l0, HID, HID);
    k_transpose_h<<<(HID * HID + TB - 1) / TB, TB>>>(p_W0t1h, W0_l1, HID, HID);
    k_transpose_h<<<(HID * HID + TB - 1) / TB, TB>>>(p_W1t1h, W1_l1, HID, HID);

    // normalization + offsets/CSR build
    k_zero_small<<<gN, TB>>>();
    k_seg_sums<<<gZ, TB>>>(vals, rows, cols);
    k_cards<<<gN, TB>>>();
    k_dsums<<<gZ, TB>>>(vals, rows, cols);
    k_valsnt<<<gZ, TB>>>(vals, rows, cols);
    k_scanA_g<<<NBLK_N, 1024>>>(p_counts, p_offs, p_bsum_n, N_NODES);
    k_scanA_g<<<NBLK_E, 1024>>>(p_ecounts, p_eoffs, p_bsum_e, N_EDGES);
    k_scanB_g<<<1, 32>>>(p_bsum_n, NBLK_N);
    k_scanB_g<<<1, 32>>>(p_bsum_e, NBLK_E);
    k_scanC_g<<<gN, TB>>>(p_offs, p_bsum_n, N_NODES);
    k_scanC_g<<<(N_EDGES + TB - 1) / TB, TB>>>(p_eoffs, p_bsum_e, N_EDGES);
    k_fill_csr<<<gZ, TB>>>(rows);

    dim3 gemm_grid(HID / 128, (N_EDGES + 127) / 128);

    // ---- layer 0 ----
    k_agg_edges64<<<N_EDGES, IN_CH>>>(x_in, rows);
    k_gemm_f16<1><<<gemm_grid, 256>>>(p_agg_h, p_W0t0h, b1_l0, p_x1h, N_EDGES, IN_CH);
    k_gemm_f16<0><<<gemm_grid, 256>>>(p_x1h, p_W1t0h, nullptr, p_M1, N_EDGES, HID);
    k_gather_nodes<<<N_NODES, 64>>>(b0_l0, cols);

    // ---- layer 1 ----
    k_agg_edges256<<<N_EDGES, 64>>>(p_x0, rows);
    k_gemm_f16<1><<<gemm_grid, 256>>>(p_agg_h, p_W0t1h, b1_l1, p_x1h, N_EDGES, HID);
    k_gemm_f16<0><<<gemm_grid, 256>>>(p_x1h, p_W1t1h, nullptr, p_M1, N_EDGES, HID);
    k_gather_nodes<<<N_NODES, 64>>>(b0_l1, cols);

    // ---- pool + head ----
    k_maxpool<<<400, HID>>>();
    k_final<<<1, HID>>>(lin_w, lin_b, out);
}

// round 6
// speedup vs baseline: 4.0034x; 1.1093x over previous
#include <cuda_runtime.h>
#include <cuda_fp16.h>
#include <math.h>
#include <stdint.h>

// ---------------- problem constants ------------------------------------------
#define N_NODES 100000
#define N_EDGES 50000
#define NNZ     400000
#define IN_CH   64
#define HID     256

// ---------------- device scratch ----------------------------------------------
__device__ float g_edge_sum[N_EDGES];
__device__ float g_node_sum[N_NODES];
__device__ float g_edge_card[N_EDGES];
__device__ float g_node_card[N_NODES];
__device__ float g_d0[N_NODES];
__device__ float g_d1[N_EDGES];
__device__ float g_vals_n[NNZ];
__device__ float g_vals_t[NNZ];
__device__ int   g_counts[N_NODES];
__device__ int   g_offs[N_NODES];
__device__ int   g_cursor[N_NODES];
__device__ int   g_ecounts[N_EDGES];
__device__ int   g_eoffs[N_EDGES];
__device__ int   g_csr[NNZ];
__device__ int   g_bsum_n[128];
__device__ int   g_bsum_e[128];
__device__ __align__(16) __half g_agg_h[N_EDGES * HID];   // GEMM1 input (half)
__device__ __align__(16) __half g_x1h  [N_EDGES * HID];   // GEMM1 out / GEMM2 in
__device__ __align__(16) __half g_M1h  [N_EDGES * HID];   // GEMM2 out (half)
__device__ __align__(16) __half g_x0h  [N_NODES * HID];   // node features (half)
__device__ float g_pooled[HID];
// pre-transposed half weights: [N=HID rows, K cols] row-major
__device__ __align__(16) __half g_W0t0h[HID * IN_CH];
__device__ __align__(16) __half g_W1t0h[HID * HID];
__device__ __align__(16) __half g_W0t1h[HID * HID];
__device__ __align__(16) __half g_W1t1h[HID * HID];

// ---------------- small init ---------------------------------------------------
__global__ void k_zero_small() {
    int i = blockIdx.x * blockDim.x + threadIdx.x;
    if (i < N_NODES) { g_node_sum[i] = 0.f; g_d0[i] = 0.f; g_counts[i] = 0; g_cursor[i] = 0; }
    if (i < N_EDGES) { g_edge_sum[i] = 0.f; g_d1[i] = 0.f; g_ecounts[i] = 0; }
    if (i < HID)     { g_pooled[i] = 0.f; }
}

// ---------------- normalization ------------------------------------------------
__global__ void k_seg_sums(const float* __restrict__ vals, const int* __restrict__ rows,
                           const int* __restrict__ cols) {
    int k = blockIdx.x * blockDim.x + threadIdx.x;
    if (k >= NNZ) return;
    float v = vals[k];
    atomicAdd(&g_edge_sum[cols[k]], v);
    atomicAdd(&g_node_sum[rows[k]], v);
}

__global__ void k_cards() {
    int i = blockIdx.x * blockDim.x + threadIdx.x;
    if (i < N_NODES) g_node_card[i] = powf(g_node_sum[i], -0.5f);
    if (i < N_EDGES) g_edge_card[i] = powf(g_edge_sum[i], -1.5f);
}

__global__ void k_dsums(const float* __restrict__ vals, const int* __restrict__ rows,
                        const int* __restrict__ cols) {
    int k = blockIdx.x * blockDim.x + threadIdx.x;
    if (k >= NNZ) return;
    float nz = (vals[k] != 0.f) ? 1.f : 0.f;
    atomicAdd(&g_d0[rows[k]], g_edge_card[cols[k]] * nz);
    atomicAdd(&g_d1[cols[k]], g_node_card[rows[k]] * nz);
}

__global__ void k_valsnt(const float* __restrict__ vals, const int* __restrict__ rows,
                         const int* __restrict__ cols) {
    int k = blockIdx.x * blockDim.x + threadIdx.x;
    if (k >= NNZ) return;
    int r = rows[k], c = cols[k];
    float v = vals[k];
    g_vals_n[k] = v * g_edge_card[c] / g_d0[r];
    g_vals_t[k] = v * g_node_card[r] / g_d1[c];
    atomicAdd(&g_counts[r], 1);
    atomicAdd(&g_ecounts[c], 1);
}

// ---------------- generic exclusive scan (two-level) ---------------------------
__global__ void k_scanA_g(const int* __restrict__ in, int* __restrict__ out,
                          int* __restrict__ bsum, int n) {
    __shared__ int sh[1024];
    int b = blockIdx.x, t = threadIdx.x;
    int i = b * 1024 + t;
    int v = (i < n) ? in[i] : 0;
    sh[t] = v;
    __syncthreads();
    for (int d = 1; d < 1024; d <<= 1) {
        int add = (t >= d) ? sh[t - d] : 0;
        __syncthreads();
        sh[t] += add;
        __syncthreads();
    }
    if (i < n) out[i] = sh[t] - v;
    if (t == 1023) bsum[b] = sh[t];
}

__global__ void k_scanB_g(int* __restrict__ bsum, int nb) {
    if (threadIdx.x == 0) {
        int acc = 0;
        for (int i = 0; i < nb; i++) { int t = bsum[i]; bsum[i] = acc; acc += t; }
    }
}

__global__ void k_scanC_g(int* __restrict__ out, const int* __restrict__ bsum, int n) {
    int i = blockIdx.x * blockDim.x + threadIdx.x;
    if (i < n) out[i] += bsum[i >> 10];
}

__global__ void k_fill_csr(const int* __restrict__ rows) {
    int k = blockIdx.x * blockDim.x + threadIdx.x;
    if (k >= NNZ) return;
    int v = rows[k];
    int p = g_offs[v] + atomicAdd(&g_cursor[v], 1);
    g_csr[p] = k;
}

// ---------------- weight transpose+convert: dst[n*K+k] = half(src[k*N+n]) -----
__global__ void k_transpose_h(__half* __restrict__ dst, const float* __restrict__ src,
                              int K, int N) {
    int i = blockIdx.x * blockDim.x + threadIdx.x;
    if (i >= K * N) return;
    int k = i / N, n = i % N;
    dst[n * K + k] = __float2half(src[i]);
}

// ---------------- node -> edge aggregation -------------------------------------
// layer 0: x float [N_NODES, 64] -> agg half
__global__ void k_agg_edges64(const float* __restrict__ x, const int* __restrict__ rows) {
    int e = blockIdx.x;
    int c = threadIdx.x;   // 0..63
    int lo = g_eoffs[e];
    int hi = lo + g_ecounts[e];
    float acc = 0.f;
    for (int k = lo; k < hi; k++)
        acc += g_vals_t[k] * x[rows[k] * IN_CH + c];
    g_agg_h[e * IN_CH + c] = __float2half(acc);
}

// layer 1: x half [N_NODES, 256] -> agg half. 64 threads x 4 halfs.
__global__ void k_agg_edges256h(const int* __restrict__ rows) {
    int e = blockIdx.x;
    int c = threadIdx.x;   // 0..63, handles halfs 4c..4c+3
    int lo = g_eoffs[e];
    int hi = lo + g_ecounts[e];
    float4 acc = make_float4(0.f, 0.f, 0.f, 0.f);
    for (int k = lo; k < hi; k++) {
        float vt = g_vals_t[k];
        uint2 u = *reinterpret_cast<const uint2*>(&g_x0h[rows[k] * HID + c * 4]);
        __half2 h0 = *reinterpret_cast<__half2*>(&u.x);
        __half2 h1 = *reinterpret_cast<__half2*>(&u.y);
        float2 f0 = __half22float2(h0);
        float2 f1 = __half22float2(h1);
        acc.x += vt * f0.x; acc.y += vt * f0.y;
        acc.z += vt * f1.x; acc.w += vt * f1.y;
    }
    __half2 o0 = __floats2half2_rn(acc.x, acc.y);
    __half2 o1 = __floats2half2_rn(acc.z, acc.w);
    uint2 o = make_uint2(*reinterpret_cast<uint32_t*>(&o0), *reinterpret_cast<uint32_t*>(&o1));
    *reinterpret_cast<uint2*>(&g_agg_h[e * HID + c * 4]) = o;
}

// ---------------- fp16 tensor-core GEMM ----------------------------------------
// C = A(MxK, half) @ Bt(256xK, half)^T ; BM=128, BN=128, BK=32.
// MODE 1: half out + bias + relu.  MODE 2: half out plain.

__device__ __forceinline__ void mma_f16(float c[4], uint32_t a0, uint32_t a1,
                                        uint32_t a2, uint32_t a3,
                                        uint32_t b0, uint32_t b1) {
    asm volatile(
        "mma.sync.aligned.m16n8k16.row.col.f32.f16.f16.f32 "
        "{%0,%1,%2,%3}, {%4,%5,%6,%7}, {%8,%9}, {%0,%1,%2,%3};\n"
        : "+f"(c[0]), "+f"(c[1]), "+f"(c[2]), "+f"(c[3])
        : "r"(a0), "r"(a1), "r"(a2), "r"(a3), "r"(b0), "r"(b1));
}

#define HS_STRIDE 40   // halfs; conflict-free for the 8x4 fragment pattern

template <int MODE>
__global__ __launch_bounds__(256)
void k_gemm_f16(const __half* __restrict__ A, const __half* __restrict__ Bt,
                const float* __restrict__ bias, __half* __restrict__ C,
                int M, int K) {
    __shared__ __half As[128 * HS_STRIDE];
    __shared__ __half Bs[128 * HS_STRIDE];
    const int N = HID;
    int tid = threadIdx.x;
    int lane = tid & 31, wid = tid >> 5;
    int wm = wid & 3, wn = wid >> 2;
    int g = lane >> 2, tig = lane & 3;
    int bm = blockIdx.y * 128, bn = blockIdx.x * 128;

    float acc[2][8][4];
    #pragma unroll
    for (int mi = 0; mi < 2; mi++)
        #pragma unroll
        for (int ni = 0; ni < 8; ni++)
            #pragma unroll
            for (int r = 0; r < 4; r++) acc[mi][ni][r] = 0.f;

    int sm = tid >> 1;
    int skh = (tid & 1) * 16;
    uint4 pa0, pa1, pb0, pb1;

    {
        const __half* Ap = A + (size_t)(bm + sm) * K + skh;
        if (bm + sm < M) {
            pa0 = *reinterpret_cast<const uint4*>(Ap);
            pa1 = *reinterpret_cast<const uint4*>(Ap + 8);
        } else {
            pa0 = make_uint4(0, 0, 0, 0); pa1 = pa0;
        }
        const __half* Bp = Bt + (size_t)(bn + sm) * K + skh;
        pb0 = *reinterpret_cast<const uint4*>(Bp);
        pb1 = *reinterpret_cast<const uint4*>(Bp + 8);
    }

    for (int k0 = 0; k0 < K; k0 += 32) {
        *reinterpret_cast<uint4*>(&As[sm * HS_STRIDE + skh])     = pa0;
        *reinterpret_cast<uint4*>(&As[sm * HS_STRIDE + skh + 8]) = pa1;
        *reinterpret_cast<uint4*>(&Bs[sm * HS_STRIDE + skh])     = pb0;
        *reinterpret_cast<uint4*>(&Bs[sm * HS_STRIDE + skh + 8]) = pb1;
        __syncthreads();

        int kn = k0 + 32;
        if (kn < K) {
            const __half* Ap = A + (size_t)(bm + sm) * K + kn + skh;
            if (bm + sm < M) {
                pa0 = *reinterpret_cast<const uint4*>(Ap);
                pa1 = *reinterpret_cast<const uint4*>(Ap + 8);
            } else {
                pa0 = make_uint4(0, 0, 0, 0); pa1 = pa0;
            }
            const __half* Bp = Bt + (size_t)(bn + sm) * K + kn + skh;
            pb0 = *reinterpret_cast<const uint4*>(Bp);
            pb1 = *reinterpret_cast<const uint4*>(Bp + 8);
        }

        #pragma unroll
        for (int ks = 0; ks < 32; ks += 16) {
            uint32_t a[2][4], b[8][2];
            #pragma unroll
            for (int mi = 0; mi < 2; mi++) {
                int mrow = wm * 32 + mi * 16 + g;
                a[mi][0] = *reinterpret_cast<const uint32_t*>(&As[(mrow    ) * HS_STRIDE + ks + 2 * tig]);
                a[mi][1] = *reinterpret_cast<const uint32_t*>(&As[(mrow + 8) * HS_STRIDE + ks + 2 * tig]);
                a[mi][2] = *reinterpret_cast<const uint32_t*>(&As[(mrow    ) * HS_STRIDE + ks + 2 * tig + 8]);
                a[mi][3] = *reinterpret_cast<const uint32_t*>(&As[(mrow + 8) * HS_STRIDE + ks + 2 * tig + 8]);
            }
            #pragma unroll
            for (int ni = 0; ni < 8; ni++) {
                int ncol = wn * 64 + ni * 8 + g;
                b[ni][0] = *reinterpret_cast<const uint32_t*>(&Bs[ncol * HS_STRIDE + ks + 2 * tig]);
                b[ni][1] = *reinterpret_cast<const uint32_t*>(&Bs[ncol * HS_STRIDE + ks + 2 * tig + 8]);
            }
            #pragma unroll
            for (int mi = 0; mi < 2; mi++)
                #pragma unroll
                for (int ni = 0; ni < 8; ni++)
                    mma_f16(acc[mi][ni], a[mi][0], a[mi][1], a[mi][2], a[mi][3],
                            b[ni][0], b[ni][1]);
        }
        __syncthreads();
    }

    #pragma unroll
    for (int mi = 0; mi < 2; mi++) {
        #pragma unroll
        for (int ni = 0; ni < 8; ni++) {
            int row0 = bm + wm * 32 + mi * 16 + g;
            int col0 = bn + wn * 64 + ni * 8 + 2 * tig;
            float v0 = acc[mi][ni][0], v1 = acc[mi][ni][1];
            float v2 = acc[mi][ni][2], v3 = acc[mi][ni][3];
            if (MODE == 1) {
                float bv0 = bias[col0], bv1 = bias[col0 + 1];
                v0 = fmaxf(v0 + bv0, 0.f); v1 = fmaxf(v1 + bv1, 0.f);
                v2 = fmaxf(v2 + bv0, 0.f); v3 = fmaxf(v3 + bv1, 0.f);
            }
            __half2 h0 = __floats2half2_rn(v0, v1);
            __half2 h1 = __floats2half2_rn(v2, v3);
            if (row0 < M)
                *reinterpret_cast<__half2*>(&C[(size_t)row0 * N + col0]) = h0;
            if (row0 + 8 < M)
                *reinterpret_cast<__half2*>(&C[(size_t)(row0 + 8) * N + col0]) = h1;
        }
    }
}

// ---------------- edge -> node gather via row-CSR (+bias, relu) ---------------
// reads M1h (half rows), accumulates float, writes x0h (half). 64 thr x 4 halfs.
__global__ void k_gather_nodes_h(const float* __restrict__ b0, const int* __restrict__ cols) {
    int v = blockIdx.x;
    int c = threadIdx.x;   // 0..63
    int off = g_offs[v];
    int n   = g_counts[v];
    float4 acc = reinterpret_cast<const float4*>(b0)[c];
    for (int j = 0; j < n; j++) {
        int k = g_csr[off + j];
        float vn = g_vals_n[k];
        uint2 u = *reinterpret_cast<const uint2*>(&g_M1h[cols[k] * HID + c * 4]);
        __half2 h0 = *reinterpret_cast<__half2*>(&u.x);
        __half2 h1 = *reinterpret_cast<__half2*>(&u.y);
        float2 f0 = __half22float2(h0);
        float2 f1 = __half22float2(h1);
        acc.x += vn * f0.x; acc.y += vn * f0.y;
        acc.z += vn * f1.x; acc.w += vn * f1.y;
    }
    acc.x = fmaxf(acc.x, 0.f); acc.y = fmaxf(acc.y, 0.f);
    acc.z = fmaxf(acc.z, 0.f); acc.w = fmaxf(acc.w, 0.f);
    __half2 o0 = __floats2half2_rn(acc.x, acc.y);
    __half2 o1 = __floats2half2_rn(acc.z, acc.w);
    uint2 o = make_uint2(*reinterpret_cast<uint32_t*>(&o0), *reinterpret_cast<uint32_t*>(&o1));
    *reinterpret_cast<uint2*>(&g_x0h[v * HID + c * 4]) = o;
}

// ---------------- max pool over nodes (half input) + final dot -----------------
__global__ void k_maxpool() {
    int c = threadIdx.x;   // 0..255 column
    int rb = blockIdx.x;
    const int RPB = (N_NODES + 399) / 400;
    int r0 = rb * RPB;
    int r1 = min(r0 + RPB, N_NODES);
    float m = 0.f;
    for (int r = r0; r < r1; r++)
        m = fmaxf(m, __half2float(g_x0h[r * HID + c]));
    atomicMax((int*)&g_pooled[c], __float_as_int(m));
}

__global__ void k_final(const float* __restrict__ lin_w, const float* __restrict__ lin_b,
                        float* __restrict__ out) {
    __shared__ float sh[256];
    int c = threadIdx.x;
    sh[c] = g_pooled[c] * lin_w[c];
    __syncthreads();
    for (int s = 128; s > 0; s >>= 1) {
        if (c < s) sh[c] += sh[c + s];
        __syncthreads();
    }
    if (c == 0) out[0] = sh[0] + lin_b[0];
}

// ---------------- launch ---------------------------------------------------------
extern "C" void kernel_launch(void* const* d_in, const int* in_sizes, int n_in,
                              void* d_out, int out_size) {
    const float* x_in  = (const float*)d_in[0];
    const float* vals  = (const float*)d_in[1];
    const int*   rows  = (const int*)  d_in[2];
    const int*   cols  = (const int*)  d_in[3];
    const float* W0_l0 = (const float*)d_in[4];
    const float* W1_l0 = (const float*)d_in[5];
    const float* b1_l0 = (const float*)d_in[6];
    const float* b0_l0 = (const float*)d_in[7];
    const float* W0_l1 = (const float*)d_in[8];
    const float* W1_l1 = (const float*)d_in[9];
    const float* b1_l1 = (const float*)d_in[10];
    const float* b0_l1 = (const float*)d_in[11];
    const float* lin_w = (const float*)d_in[12];
    const float* lin_b = (const float*)d_in[13];
    float* out = (float*)d_out;

    __half *p_agg_h, *p_x1h, *p_M1h, *p_W0t0h, *p_W1t0h, *p_W0t1h, *p_W1t1h;
    int *p_counts, *p_offs, *p_ecounts, *p_eoffs, *p_bsum_n, *p_bsum_e;
    cudaGetSymbolAddress((void**)&p_agg_h, g_agg_h);
    cudaGetSymbolAddress((void**)&p_x1h,   g_x1h);
    cudaGetSymbolAddress((void**)&p_M1h,   g_M1h);
    cudaGetSymbolAddress((void**)&p_W0t0h, g_W0t0h);
    cudaGetSymbolAddress((void**)&p_W1t0h, g_W1t0h);
    cudaGetSymbolAddress((void**)&p_W0t1h, g_W0t1h);
    cudaGetSymbolAddress((void**)&p_W1t1h, g_W1t1h);
    cudaGetSymbolAddress((void**)&p_counts,  g_counts);
    cudaGetSymbolAddress((void**)&p_offs,    g_offs);
    cudaGetSymbolAddress((void**)&p_ecounts, g_ecounts);
    cudaGetSymbolAddress((void**)&p_eoffs,   g_eoffs);
    cudaGetSymbolAddress((void**)&p_bsum_n,  g_bsum_n);
    cudaGetSymbolAddress((void**)&p_bsum_e,  g_bsum_e);

    const int TB = 256;
    const int gN = (N_NODES + TB - 1) / TB;
    const int gZ = (NNZ + TB - 1) / TB;
    const int NBLK_N = (N_NODES + 1023) / 1024;
    const int NBLK_E = (N_EDGES + 1023) / 1024;

    // weight transposes + convert to half
    k_transpose_h<<<(IN_CH * HID + TB - 1) / TB, TB>>>(p_W0t0h, W0_l0, IN_CH, HID);
    k_transpose_h<<<(HID * HID + TB - 1) / TB, TB>>>(p_W1t0h, W1_l0, HID, HID);
    k_transpose_h<<<(HID * HID + TB - 1) / TB, TB>>>(p_W0t1h, W0_l1, HID, HID);
    k_transpose_h<<<(HID * HID + TB - 1) / TB, TB>>>(p_W1t1h, W1_l1, HID, HID);

    // normalization + offsets/CSR build
    k_zero_small<<<gN, TB>>>();
    k_seg_sums<<<gZ, TB>>>(vals, rows, cols);
    k_cards<<<gN, TB>>>();
    k_dsums<<<gZ, TB>>>(vals, rows, cols);
    k_valsnt<<<gZ, TB>>>(vals, rows, cols);
    k_scanA_g<<<NBLK_N, 1024>>>(p_counts, p_offs, p_bsum_n, N_NODES);
    k_scanA_g<<<NBLK_E, 1024>>>(p_ecounts, p_eoffs, p_bsum_e, N_EDGES);
    k_scanB_g<<<1, 32>>>(p_bsum_n, NBLK_N);
    k_scanB_g<<<1, 32>>>(p_bsum_e, NBLK_E);
    k_scanC_g<<<gN, TB>>>(p_offs, p_bsum_n, N_NODES);
    k_scanC_g<<<(N_EDGES + TB - 1) / TB, TB>>>(p_eoffs, p_bsum_e, N_EDGES);
    k_fill_csr<<<gZ, TB>>>(rows);

    dim3 gemm_grid(HID / 128, (N_EDGES + 127) / 128);

    // ---- layer 0 ----
    k_agg_edges64<<<N_EDGES, IN_CH>>>(x_in, rows);
    k_gemm_f16<1><<<gemm_grid, 256>>>(p_agg_h, p_W0t0h, b1_l0, p_x1h, N_EDGES, IN_CH);
    k_gemm_f16<2><<<gemm_grid, 256>>>(p_x1h, p_W1t0h, nullptr, p_M1h, N_EDGES, HID);
    k_gather_nodes_h<<<N_NODES, 64>>>(b0_l0, cols);

    // ---- layer 1 ----
    k_agg_edges256h<<<N_EDGES, 64>>>(rows);
    k_gemm_f16<1><<<gemm_grid, 256>>>(p_agg_h, p_W0t1h, b1_l1, p_x1h, N_EDGES, HID);
    k_gemm_f16<2><<<gemm_grid, 256>>>(p_x1h, p_W1t1h, nullptr, p_M1h, N_EDGES, HID);
    k_gather_nodes_h<<<N_NODES, 64>>>(b0_l1, cols);

    // ---- pool + head ----
    k_maxpool<<<400, HID>>>();
    k_final<<<1, HID>>>(lin_w, lin_b, out);
}